// round 10
// baseline (speedup 1.0000x reference)
#include <cuda_runtime.h>
#include <cuda_bf16.h>

#define TT 512
#define LL 62
#define KK 64
#define GG 4
#define FULLM 0xffffffffu

__global__ void init_out_kernel(float* out) { out[0] = 0.0f; }

__device__ __forceinline__ __nv_bfloat162 ubf2(unsigned v) {
    __nv_bfloat162 r;
    *reinterpret_cast<unsigned*>(&r) = v;
    return r;
}

// dot for this lane's two columns: d_j = sum_{k=0}^{63} u[k] * E[k][j].
// u_sh holds 32 bf16x2 pairs (u[2p], u[2p+1]); E*[p] matches pairwise.
// Pairs p=31 (states 62,63) have E = exp(-10000) = 0.
__device__ __forceinline__ float2 dot_smem(const __nv_bfloat162* __restrict__ u_sh,
                                           const __nv_bfloat162* __restrict__ E0,
                                           const __nv_bfloat162* __restrict__ E1) {
    const uint4* up = reinterpret_cast<const uint4*>(u_sh);
    __nv_bfloat162 z = ubf2(0u);
    __nv_bfloat162 a0 = z, a1 = z, a2 = z, a3 = z;   // column j0
    __nv_bfloat162 b0 = z, b1 = z, b2 = z, b3 = z;   // column j1
    #pragma unroll
    for (int q = 0; q < 8; ++q) {
        const uint4 v = up[q];
        a0 = __hfma2(ubf2(v.x), E0[4 * q + 0], a0);
        b0 = __hfma2(ubf2(v.x), E1[4 * q + 0], b0);
        a1 = __hfma2(ubf2(v.y), E0[4 * q + 1], a1);
        b1 = __hfma2(ubf2(v.y), E1[4 * q + 1], b1);
        a2 = __hfma2(ubf2(v.z), E0[4 * q + 2], a2);
        b2 = __hfma2(ubf2(v.z), E1[4 * q + 2], b2);
        a3 = __hfma2(ubf2(v.w), E0[4 * q + 3], a3);
        b3 = __hfma2(ubf2(v.w), E1[4 * q + 3], b3);
    }
    const __nv_bfloat162 sa = __hadd2(__hadd2(a0, a1), __hadd2(a2, a3));
    const __nv_bfloat162 sb = __hadd2(__hadd2(b0, b1), __hadd2(b2, b3));
    const float2 fa = __bfloat1622float2(sa);
    const float2 fb = __bfloat1622float2(sb);
    return make_float2(fa.x + fa.y, fb.x + fb.y);
}

__global__ __launch_bounds__(32) void crf_warp_kernel(
    const float* __restrict__ pred,      // [B, T, L]
    const int*   __restrict__ ref,       // [B, T]
    const int*   __restrict__ seq_len,   // [B]
    const float* __restrict__ trans,     // [K, K]
    float* __restrict__ out)
{
    const int b    = blockIdx.x;
    const int lane = threadIdx.x;
    const int j0   = 2 * lane;           // this lane's two columns
    const int j1   = j0 + 1;

    __shared__ __align__(16) __nv_bfloat162 u_sh[2][32];

    const float* predb = pred + (size_t)b * TT * LL;
    const int*   refb  = ref  + (size_t)b * TT;
    const int    sl    = seq_len[b];

    // E pairs for columns j0, j1 (exp(trans), rows 62/63 -> exactly 0)
    __nv_bfloat162 E0[32], E1[32];
    #pragma unroll
    for (int p = 0; p < 32; ++p) {
        E0[p] = __floats2bfloat162_rn(__expf(trans[(2 * p) * KK + j0]),
                                      __expf(trans[(2 * p + 1) * KK + j0]));
        E1[p] = __floats2bfloat162_rn(__expf(trans[(2 * p) * KK + j1]),
                                      __expf(trans[(2 * p + 1) * KK + j1]));
    }

    // u = exp(alpha - c); labels 1 at c = -1000, start/end (lane 31) 0.
    const bool lab = (lane < 31);
    u_sh[0][lane] = __floats2bfloat162_rn(lab ? 1.0f : 0.0f, lab ? 1.0f : 0.0f);
    float c = -1000.0f;
    int cur = 0;

    // eobs pipeline: one float2 LDG + 2 exp per lane per step, one group ahead
    float2 eA[GG], eB[GG];
    #pragma unroll
    for (int i = 0; i < GG; ++i) {
        if (lab) {
            const float2 o = __ldg((const float2*)&predb[i * LL + j0]);
            eA[i] = make_float2(__expf(o.x), __expf(o.y));
        } else eA[i] = make_float2(0.0f, 0.0f);
    }

    int s = 1;
    while (s + GG <= sl + 1) {           // steps s..s+GG-1, all emission steps
        #pragma unroll
        for (int i = 0; i < GG; ++i) {   // prefetch next group
            const int row = s + GG - 1 + i;
            if (lab && row < TT) {
                const float2 o = __ldg((const float2*)&predb[row * LL + j0]);
                eB[i] = make_float2(__expf(o.x), __expf(o.y));
            } else eB[i] = make_float2(0.0f, 0.0f);
        }
        #pragma unroll
        for (int i = 0; i < GG; ++i) {
            __syncwarp();
            float sc = 1.0f;
            if (i == 0 && s != 1) {      // deferred renorm every GG steps
                const float u0 = __bfloat162float(u_sh[cur][0].x);
                sc = __frcp_rn(u0);
                c += __logf(u0);
            }
            const float2 d = dot_smem(u_sh[cur], E0, E1);
            u_sh[cur ^ 1][lane] =
                __floats2bfloat162_rn(eA[i].x * sc * d.x, eA[i].y * sc * d.y);
            cur ^= 1;
        }
        #pragma unroll
        for (int i = 0; i < GG; ++i) eA[i] = eB[i];
        s += GG;
    }

    const int rem = sl + 1 - s;          // 0..GG-1 remaining emission steps
    #pragma unroll
    for (int i = 0; i < GG - 1; ++i) {
        if (i >= rem) break;
        __syncwarp();
        float sc = 1.0f;
        if (i == 0 && s != 1) {
            const float u0 = __bfloat162float(u_sh[cur][0].x);
            sc = __frcp_rn(u0);
            c += __logf(u0);
        }
        const float2 d = dot_smem(u_sh[cur], E0, E1);
        u_sh[cur ^ 1][lane] =
            __floats2bfloat162_rn(eA[i].x * sc * d.x, eA[i].y * sc * d.y);
        cur ^= 1;
    }
    __syncwarp();

    // ---- boundary step (sl+1) in log domain over all 64 columns ----
    const float2 dB = dot_smem(u_sh[cur], E0, E1);
    float ob0, ob1;
    if (lab) {
        const float2 base = (sl < TT) ? __ldg((const float2*)&predb[sl * LL + j0])
                                      : make_float2(0.0f, 0.0f);
        ob0 = base.x - 1000.0f;
        ob1 = base.y - 1000.0f;
    } else {
        ob0 = -1000.0f;                  // start column (62)
        ob1 = 0.0f;                      // end column (63)
    }
    const float al0 = ob0 + c + __logf(dB.x);
    const float al1 = ob1 + c + __logf(dB.y);

    // ---- logsumexp over the 64 columns ----
    float m = fmaxf(al0, al1);
    #pragma unroll
    for (int off = 16; off; off >>= 1)
        m = fmaxf(m, __shfl_xor_sync(FULLM, m, off));
    float S = __expf(al0 - m) + __expf(al1 - m);
    #pragma unroll
    for (int off = 16; off; off >>= 1)
        S += __shfl_xor_sync(FULLM, S, off);
    const float lse = m + __logf(S);

    // ---- gold score, exact fp32 ----
    float gold = 0.0f;
    for (int t = lane; t < sl; t += 32)
        gold += predb[t * LL + refb[t]];
    for (int t = lane; t <= sl; t += 32) {
        const int from = (t == 0)  ? LL       : refb[t - 1];
        const int to   = (t == sl) ? (LL + 1) : refb[t];
        gold += trans[from * KK + to];
    }
    #pragma unroll
    for (int off = 16; off; off >>= 1)
        gold += __shfl_xor_sync(FULLM, gold, off);

    if (lane == 0)
        atomicAdd(out, lse - gold);
}

extern "C" void kernel_launch(void* const* d_in, const int* in_sizes, int n_in,
                              void* d_out, int out_size)
{
    const float* pred    = (const float*)d_in[0];
    const int*   ref     = (const int*)d_in[1];
    const int*   seq_len = (const int*)d_in[2];
    const float* trans   = (const float*)d_in[3];
    float*       out     = (float*)d_out;

    const int B = in_sizes[2];   // 1024

    init_out_kernel<<<1, 1>>>(out);
    crf_warp_kernel<<<B, 32>>>(pred, ref, seq_len, trans, out);
}

// round 11
// speedup vs baseline: 1.3390x; 1.3390x over previous
#include <cuda_runtime.h>
#include <cuda_bf16.h>

#define TT 512
#define LL 62
#define KK 64
#define GG 8
#define NTH 128

__global__ void init_out_kernel(float* out) { out[0] = 0.0f; }

__device__ __forceinline__ __nv_bfloat162 ubf2(unsigned v) {
    __nv_bfloat162 r;
    *reinterpret_cast<unsigned*>(&r) = v;
    return r;
}

#define BAR(id) asm volatile("bar.sync %0, 64;" :: "r"(id) : "memory")

// dot = sum over 64 states of x[k] * Epk[k-pair], x bf16 in smem (broadcast
// LDS.128), Epk bf16x2 pairs in registers. Zero rows/cols make pad exact.
__device__ __forceinline__ float dot64h(const __nv_bfloat16* __restrict__ xbuf,
                                        const __nv_bfloat162* __restrict__ Epk) {
    const uint4* up = reinterpret_cast<const uint4*>(xbuf);
    __nv_bfloat162 z = ubf2(0u);
    __nv_bfloat162 a0 = z, a1 = z, a2 = z, a3 = z;
    #pragma unroll
    for (int q = 0; q < 8; ++q) {
        const uint4 v = up[q];
        a0 = __hfma2(ubf2(v.x), Epk[4 * q + 0], a0);
        a1 = __hfma2(ubf2(v.y), Epk[4 * q + 1], a1);
        a2 = __hfma2(ubf2(v.z), Epk[4 * q + 2], a2);
        a3 = __hfma2(ubf2(v.w), Epk[4 * q + 3], a3);
    }
    const __nv_bfloat162 s = __hadd2(__hadd2(a0, a1), __hadd2(a2, a3));
    const float2 f = __bfloat1622float2(s);
    return f.x + f.y;
}

__global__ __launch_bounds__(NTH) void crf_fb_kernel(
    const float* __restrict__ pred,      // [B, T, L]
    const int*   __restrict__ ref,       // [B, T]
    const int*   __restrict__ seq_len,   // [B]
    const float* __restrict__ trans,     // [K, K]
    float* __restrict__ out)
{
    const int b    = blockIdx.x;
    const int tid  = threadIdx.x;
    const int j    = tid & 63;           // state owned by this thread
    const int half = tid >> 6;           // 0 = forward pair, 1 = backward pair
    const int lane = tid & 31;
    const int wid  = tid >> 5;

    __shared__ __align__(16) __nv_bfloat16 x_sh[2][2][KK]; // [half][buf][state]
    __shared__ float uF[KK], wF[KK], cfb[2];
    __shared__ float red[4], red2[4];

    const float* predb = pred + (size_t)b * TT * LL;
    const int*   refb  = ref  + (size_t)b * TT;
    const int    sl    = seq_len[b];
    const int    m     = sl >> 1;        // forward steps; backward = sl - m

    const bool lab = (j < LL);

    // E pairs: fwd thread j needs column j of exp(trans) (k-pairs);
    // bwd thread j needs row j (column-pairs). Rows 62,63 are exactly 0.
    __nv_bfloat162 Epk[32];
    if (half == 0) {
        #pragma unroll
        for (int p = 0; p < 32; ++p)
            Epk[p] = __floats2bfloat162_rn(__expf(trans[(2 * p) * KK + j]),
                                           __expf(trans[(2 * p + 1) * KK + j]));
    } else {
        #pragma unroll
        for (int p = 0; p < 32; ++p)
            Epk[p] = __floats2bfloat162_rn(__expf(trans[j * KK + 2 * p]),
                                           __expf(trans[j * KK + 2 * p + 1]));
    }

    if (half == 0) {
        // ---------------- forward: alpha_0 .. alpha_m ----------------
        float un = lab ? 1.0f : 0.0f;    // u = exp(alpha - c), c = -1000
        float c  = -1000.0f;
        x_sh[0][0][j] = __float2bfloat16(un);
        int cur = 0;

        float eA[GG], eB[GG];
        #pragma unroll
        for (int i = 0; i < GG; ++i)
            eA[i] = lab ? __expf(__ldg(&predb[i * LL + j])) : 0.0f;

        int s = 1;
        while (s + GG <= m + 1) {        // steps s..s+GG-1 (all <= m)
            #pragma unroll
            for (int i = 0; i < GG; ++i) {
                const int row = s + GG - 1 + i;   // <= m+GG-1 < TT
                eB[i] = lab ? __expf(__ldg(&predb[row * LL + j])) : 0.0f;
            }
            #pragma unroll
            for (int i = 0; i < GG; ++i) {
                BAR(1);
                float sc = 1.0f;
                if (((i & 3) == 0) && !(i == 0 && s == 1)) {
                    const float u0 = __bfloat162float(x_sh[0][cur][0]);
                    sc = __frcp_rn(u0);
                    c += __logf(u0);
                }
                const float d = dot64h(x_sh[0][cur], Epk);
                un = eA[i] * sc * d;
                x_sh[0][cur ^ 1][j] = __float2bfloat16(un);
                cur ^= 1;
            }
            #pragma unroll
            for (int i = 0; i < GG; ++i) eA[i] = eB[i];
            s += GG;
        }
        const int rem = m + 1 - s;       // 0..GG-1
        #pragma unroll
        for (int i = 0; i < GG - 1; ++i) {
            if (i >= rem) break;
            BAR(1);
            float sc = 1.0f;
            if (((i & 3) == 0) && !(i == 0 && s == 1)) {
                const float u0 = __bfloat162float(x_sh[0][cur][0]);
                sc = __frcp_rn(u0);
                c += __logf(u0);
            }
            const float d = dot64h(x_sh[0][cur], Epk);
            un = eA[i] * sc * d;
            x_sh[0][cur ^ 1][j] = __float2bfloat16(un);
            cur ^= 1;
        }
        uF[j] = un;                      // exp(alpha_m - c_f)
        if (j == 0) cfb[0] = c;
    } else {
        // ---------------- backward: beta_sl .. beta_m ----------------
        // analytic init: beta_sl[k] = trans[k][63] (boundary row handled
        // exactly; label terms are e^{-1000}-suppressed, 0 in fp32)
        float w = __expf(trans[j * KK + 63]);
        float c = 0.0f;
        int cur = 0;
        const int N = sl - m;            // >= 1

        float eA[GG], eB[GG];
        #pragma unroll
        for (int i = 0; i < GG; ++i) {
            const int row = sl - 1 - i;
            eA[i] = (lab && row >= 0) ? __expf(__ldg(&predb[row * LL + j])) : 0.0f;
        }

        int q = 0;
        while (q + GG <= N) {
            #pragma unroll
            for (int i = 0; i < GG; ++i) {
                const int row = sl - 1 - (q + GG + i);
                eB[i] = (lab && row >= 0) ? __expf(__ldg(&predb[row * LL + j]))
                                          : 0.0f;
            }
            #pragma unroll
            for (int i = 0; i < GG; ++i) {
                float sc = 1.0f;
                if (((i & 3) == 0) && !(i == 0 && q == 0)) {
                    const float v0 = __bfloat162float(x_sh[1][cur ^ 1][0]);
                    sc = __frcp_rn(v0);
                    c += __logf(v0);
                }
                x_sh[1][cur][j] = __float2bfloat16(eA[i] * sc * w);
                BAR(2);
                w = dot64h(x_sh[1][cur], Epk);
                cur ^= 1;
            }
            #pragma unroll
            for (int i = 0; i < GG; ++i) eA[i] = eB[i];
            q += GG;
        }
        const int rem = N - q;           // 0..GG-1
        #pragma unroll
        for (int i = 0; i < GG - 1; ++i) {
            if (i >= rem) break;
            float sc = 1.0f;
            if (((i & 3) == 0) && !(i == 0 && q == 0)) {
                const float v0 = __bfloat162float(x_sh[1][cur ^ 1][0]);
                sc = __frcp_rn(v0);
                c += __logf(v0);
            }
            x_sh[1][cur][j] = __float2bfloat16(eA[i] * sc * w);
            BAR(2);
            w = dot64h(x_sh[1][cur], Epk);
            cur ^= 1;
        }
        wF[j] = w;                       // exp(beta_m - c_b)
        if (j == 0) cfb[1] = c;
    }
    __syncthreads();

    // ---- combine: logZ = c_f + c_b + log( sum_k u[k] * w[k] ) ----
    float p = (tid < KK) ? uF[tid] * wF[tid] : 0.0f;
    #pragma unroll
    for (int off = 16; off; off >>= 1)
        p += __shfl_xor_sync(0xffffffffu, p, off);
    if (lane == 0) red[wid] = p;

    // ---- gold score, exact fp32, all 128 threads ----
    float gold = 0.0f;
    for (int t = tid; t < sl; t += NTH)
        gold += predb[t * LL + refb[t]];
    for (int t = tid; t <= sl; t += NTH) {
        const int from = (t == 0)  ? LL       : refb[t - 1];
        const int to   = (t == sl) ? (LL + 1) : refb[t];
        gold += trans[from * KK + to];
    }
    #pragma unroll
    for (int off = 16; off; off >>= 1)
        gold += __shfl_xor_sync(0xffffffffu, gold, off);
    if (lane == 0) red2[wid] = gold;
    __syncthreads();

    if (tid == 0) {
        const float S    = (red[0] + red[1]) + (red[2] + red[3]);
        const float gtot = (red2[0] + red2[1]) + (red2[2] + red2[3]);
        atomicAdd(out, cfb[0] + cfb[1] + __logf(S) - gtot);
    }
}

extern "C" void kernel_launch(void* const* d_in, const int* in_sizes, int n_in,
                              void* d_out, int out_size)
{
    const float* pred    = (const float*)d_in[0];
    const int*   ref     = (const int*)d_in[1];
    const int*   seq_len = (const int*)d_in[2];
    const float* trans   = (const float*)d_in[3];
    float*       out     = (float*)d_out;

    const int B = in_sizes[2];   // 1024

    init_out_kernel<<<1, 1>>>(out);
    crf_fb_kernel<<<B, NTH>>>(pred, ref, seq_len, trans, out);
}

// round 12
// speedup vs baseline: 1.3644x; 1.0189x over previous
#include <cuda_runtime.h>
#include <cuda_bf16.h>

#define TT 512
#define LL 62
#define KK 64
#define GG 4
#define NTH 128

__global__ void init_out_kernel(float* out) { out[0] = 0.0f; }

__device__ __forceinline__ __nv_bfloat162 ubf2(unsigned v) {
    __nv_bfloat162 r;
    *reinterpret_cast<unsigned*>(&r) = v;
    return r;
}

#define BAR(id) asm volatile("bar.sync %0, 64;" :: "r"(id) : "memory")

// dot = sum over 64 states of x[k] * Epk[k-pair], x bf16 in smem (broadcast
// LDS.128), Epk bf16x2 pairs in registers. Zero rows/cols make pad exact.
__device__ __forceinline__ float dot64h(const __nv_bfloat16* __restrict__ xbuf,
                                        const __nv_bfloat162* __restrict__ Epk) {
    const uint4* up = reinterpret_cast<const uint4*>(xbuf);
    __nv_bfloat162 z = ubf2(0u);
    __nv_bfloat162 a0 = z, a1 = z, a2 = z, a3 = z;
    #pragma unroll
    for (int q = 0; q < 8; ++q) {
        const uint4 v = up[q];
        a0 = __hfma2(ubf2(v.x), Epk[4 * q + 0], a0);
        a1 = __hfma2(ubf2(v.y), Epk[4 * q + 1], a1);
        a2 = __hfma2(ubf2(v.z), Epk[4 * q + 2], a2);
        a3 = __hfma2(ubf2(v.w), Epk[4 * q + 3], a3);
    }
    const __nv_bfloat162 s = __hadd2(__hadd2(a0, a1), __hadd2(a2, a3));
    const float2 f = __bfloat1622float2(s);
    return f.x + f.y;
}

__global__ __launch_bounds__(NTH, 7) void crf_fb_kernel(
    const float* __restrict__ pred,      // [B, T, L]
    const int*   __restrict__ ref,       // [B, T]
    const int*   __restrict__ seq_len,   // [B]
    const float* __restrict__ trans,     // [K, K]
    float* __restrict__ out)
{
    const int b    = blockIdx.x;
    const int tid  = threadIdx.x;
    const int j    = tid & 63;           // state owned by this thread
    const int half = tid >> 6;           // 0 = forward pair, 1 = backward pair
    const int lane = tid & 31;
    const int wid  = tid >> 5;

    __shared__ __align__(16) __nv_bfloat16 x_sh[2][2][KK]; // [half][buf][state]
    __shared__ float uF[KK], wF[KK], cfb[2];
    __shared__ float red[4], red2[4];

    const float* predb = pred + (size_t)b * TT * LL;
    const int*   refb  = ref  + (size_t)b * TT;
    const int    sl    = seq_len[b];
    const int    m     = sl >> 1;        // forward steps; backward = sl - m

    const bool lab = (j < LL);

    // E pairs: fwd thread j uses column j of exp(trans) (k-pairs);
    // bwd thread j uses row j (column-pairs). Rows 62,63 are exactly 0.
    __nv_bfloat162 Epk[32];
    if (half == 0) {
        #pragma unroll
        for (int p = 0; p < 32; ++p)
            Epk[p] = __floats2bfloat162_rn(__expf(trans[(2 * p) * KK + j]),
                                           __expf(trans[(2 * p + 1) * KK + j]));
    } else {
        #pragma unroll
        for (int p = 0; p < 32; ++p)
            Epk[p] = __floats2bfloat162_rn(__expf(trans[j * KK + 2 * p]),
                                           __expf(trans[j * KK + 2 * p + 1]));
    }

    if (half == 0) {
        // ---------------- forward: alpha_0 .. alpha_m ----------------
        float un = lab ? 1.0f : 0.0f;    // u = exp(alpha - c), c = -1000
        float c  = -1000.0f;
        x_sh[0][0][j] = __float2bfloat16(un);
        int cur = 0;

        float eA[GG], eB[GG];
        #pragma unroll
        for (int i = 0; i < GG; ++i)
            eA[i] = lab ? __expf(__ldg(&predb[i * LL + j])) : 0.0f;

        int s = 1;
        while (s + GG <= m + 1) {        // steps s..s+GG-1 (all <= m)
            #pragma unroll
            for (int i = 0; i < GG; ++i) {
                const int row = s + GG - 1 + i;   // <= m+GG-1 < TT
                eB[i] = lab ? __expf(__ldg(&predb[row * LL + j])) : 0.0f;
            }
            #pragma unroll
            for (int i = 0; i < GG; ++i) {
                BAR(1);
                float sc = 1.0f;
                if (i == 0 && s != 1) {  // deferred renorm every GG steps
                    const float u0 = __bfloat162float(x_sh[0][cur][0]);
                    sc = __frcp_rn(u0);
                    c += __logf(u0);
                }
                const float d = dot64h(x_sh[0][cur], Epk);
                un = eA[i] * sc * d;
                x_sh[0][cur ^ 1][j] = __float2bfloat16(un);
                cur ^= 1;
            }
            #pragma unroll
            for (int i = 0; i < GG; ++i) eA[i] = eB[i];
            s += GG;
        }
        const int rem = m + 1 - s;       // 0..GG-1
        #pragma unroll
        for (int i = 0; i < GG - 1; ++i) {
            if (i >= rem) break;
            BAR(1);
            float sc = 1.0f;
            if (i == 0 && s != 1) {
                const float u0 = __bfloat162float(x_sh[0][cur][0]);
                sc = __frcp_rn(u0);
                c += __logf(u0);
            }
            const float d = dot64h(x_sh[0][cur], Epk);
            un = eA[i] * sc * d;
            x_sh[0][cur ^ 1][j] = __float2bfloat16(un);
            cur ^= 1;
        }
        uF[j] = un;                      // exp(alpha_m - c_f)
        if (j == 0) cfb[0] = c;
    } else {
        // ---------------- backward: beta_sl .. beta_m ----------------
        // analytic init: beta_sl[k] = trans[k][63] (label boundary terms are
        // e^{-1000}-suppressed -> exactly 0 in fp32, matching the reference)
        float w = __expf(trans[j * KK + 63]);
        float c = 0.0f;
        int cur = 0;
        const int N = sl - m;            // >= 1

        float eA[GG], eB[GG];
        #pragma unroll
        for (int i = 0; i < GG; ++i) {
            const int row = sl - 1 - i;
            eA[i] = (lab && row >= 0) ? __expf(__ldg(&predb[row * LL + j])) : 0.0f;
        }

        int q = 0;
        while (q + GG <= N) {
            #pragma unroll
            for (int i = 0; i < GG; ++i) {
                const int row = sl - 1 - (q + GG + i);
                eB[i] = (lab && row >= 0) ? __expf(__ldg(&predb[row * LL + j]))
                                          : 0.0f;
            }
            #pragma unroll
            for (int i = 0; i < GG; ++i) {
                float sc = 1.0f;
                if (i == 0 && q != 0) {  // deferred renorm every GG steps
                    const float v0 = __bfloat162float(x_sh[1][cur ^ 1][0]);
                    sc = __frcp_rn(v0);
                    c += __logf(v0);
                }
                x_sh[1][cur][j] = __float2bfloat16(eA[i] * sc * w);
                BAR(2);
                w = dot64h(x_sh[1][cur], Epk);
                cur ^= 1;
            }
            #pragma unroll
            for (int i = 0; i < GG; ++i) eA[i] = eB[i];
            q += GG;
        }
        const int rem = N - q;           // 0..GG-1
        #pragma unroll
        for (int i = 0; i < GG - 1; ++i) {
            if (i >= rem) break;
            float sc = 1.0f;
            if (i == 0 && q != 0) {
                const float v0 = __bfloat162float(x_sh[1][cur ^ 1][0]);
                sc = __frcp_rn(v0);
                c += __logf(v0);
            }
            x_sh[1][cur][j] = __float2bfloat16(eA[i] * sc * w);
            BAR(2);
            w = dot64h(x_sh[1][cur], Epk);
            cur ^= 1;
        }
        wF[j] = w;                       // exp(beta_m - c_b)
        if (j == 0) cfb[1] = c;
    }
    __syncthreads();

    // ---- combine: logZ = c_f + c_b + log( sum_k u[k] * w[k] ) ----
    float p = (tid < KK) ? uF[tid] * wF[tid] : 0.0f;
    #pragma unroll
    for (int off = 16; off; off >>= 1)
        p += __shfl_xor_sync(0xffffffffu, p, off);
    if (lane == 0) red[wid] = p;

    // ---- gold score, exact fp32, all 128 threads ----
    float gold = 0.0f;
    for (int t = tid; t < sl; t += NTH)
        gold += __ldg(&predb[t * LL + __ldg(&refb[t])]);
    for (int t = tid; t <= sl; t += NTH) {
        const int from = (t == 0)  ? LL       : __ldg(&refb[t - 1]);
        const int to   = (t == sl) ? (LL + 1) : __ldg(&refb[t]);
        gold += __ldg(&trans[from * KK + to]);
    }
    #pragma unroll
    for (int off = 16; off; off >>= 1)
        gold += __shfl_xor_sync(0xffffffffu, gold, off);
    if (lane == 0) red2[wid] = gold;
    __syncthreads();

    if (tid == 0) {
        const float S    = (red[0] + red[1]) + (red[2] + red[3]);
        const float gtot = (red2[0] + red2[1]) + (red2[2] + red2[3]);
        atomicAdd(out, cfb[0] + cfb[1] + __logf(S) - gtot);
    }
}

extern "C" void kernel_launch(void* const* d_in, const int* in_sizes, int n_in,
                              void* d_out, int out_size)
{
    const float* pred    = (const float*)d_in[0];
    const int*   ref     = (const int*)d_in[1];
    const int*   seq_len = (const int*)d_in[2];
    const float* trans   = (const float*)d_in[3];
    float*       out     = (float*)d_out;

    const int B = in_sizes[2];   // 1024

    init_out_kernel<<<1, 1>>>(out);
    crf_fb_kernel<<<B, NTH>>>(pred, ref, seq_len, trans, out);
}